// round 2
// baseline (speedup 1.0000x reference)
#include <cuda_runtime.h>
#include <cuda_bf16.h>
#include <math.h>

// ---------------------------------------------------------------------------
// Problem constants (fixed by the reference setup)
// ---------------------------------------------------------------------------
#define T_TOK   6400
#define D_DIM   512
#define HID     1024      // 2*LH*H + 2*AH*H
#define B_SZ    4
#define N_SEQ   2048
#define H_HEADS 4
#define AH_D    64
#define LH_D    64
#define EPS     1e-6f
#define INV_N   (1.0f/2048.0f)

// jagged offsets (tokens) and tile offsets (64-row tiles)
__device__ __constant__ int c_off[5]  = {0, 2048, 3584, 4608, 6400};

// ---------------------------------------------------------------------------
// Scratch (static device globals; no allocation allowed)
// ---------------------------------------------------------------------------
__device__ float g_xn  [T_TOK * D_DIM];   // LN(x)
__device__ float g_h   [T_TOK * HID];     // silu(xn @ uvqk): u|v|q|k
__device__ float g_attn[T_TOK * 256];     // attention output (H*LH)
__device__ float g_oin [T_TOK * 256];     // u * LN(attn)

#define FMA16(acc, a, b) \
  acc[0]+=a.x*b.x;  acc[1]+=a.x*b.y;  acc[2]+=a.x*b.z;  acc[3]+=a.x*b.w;  \
  acc[4]+=a.y*b.x;  acc[5]+=a.y*b.y;  acc[6]+=a.y*b.z;  acc[7]+=a.y*b.w;  \
  acc[8]+=a.z*b.x;  acc[9]+=a.z*b.y;  acc[10]+=a.z*b.z; acc[11]+=a.z*b.w; \
  acc[12]+=a.w*b.x; acc[13]+=a.w*b.y; acc[14]+=a.w*b.z; acc[15]+=a.w*b.w;

// ---------------------------------------------------------------------------
// Kernel 1: LayerNorm over D=512 (one block per token)
// ---------------------------------------------------------------------------
__global__ void ln_x_kernel(const float* __restrict__ x) {
    int t = blockIdx.x;
    int tid = threadIdx.x;
    const float* row = x + (size_t)t * D_DIM;
    float v0 = row[tid];
    float v1 = row[tid + 256];
    float s = v0 + v1;
    float q = v0 * v0 + v1 * v1;
    __shared__ float sbuf[18];
    #pragma unroll
    for (int o = 16; o > 0; o >>= 1) {
        s += __shfl_down_sync(0xffffffffu, s, o);
        q += __shfl_down_sync(0xffffffffu, q, o);
    }
    int w = tid >> 5;
    if ((tid & 31) == 0) { sbuf[w] = s; sbuf[w + 8] = q; }
    __syncthreads();
    if (tid == 0) {
        float S = 0.f, Q = 0.f;
        #pragma unroll
        for (int i = 0; i < 8; i++) { S += sbuf[i]; Q += sbuf[i + 8]; }
        float m = S * (1.0f / D_DIM);
        float var = Q * (1.0f / D_DIM) - m * m;
        sbuf[16] = m;
        sbuf[17] = rsqrtf(var + EPS);
    }
    __syncthreads();
    float m = sbuf[16], r = sbuf[17];
    g_xn[(size_t)t * D_DIM + tid]       = (v0 - m) * r;
    g_xn[(size_t)t * D_DIM + tid + 256] = (v1 - m) * r;
}

// ---------------------------------------------------------------------------
// Kernel 2: h = silu(xn @ uvqk)   [6400,512]@[512,1024]
// 64x64 tiles, BK=16, 256 threads, 4x4 micro-tile
// ---------------------------------------------------------------------------
__global__ void gemm_uvqk_kernel(const float* __restrict__ W) {
    __shared__ float As[16 * 64];
    __shared__ float Bs[16 * 64];
    int tid = threadIdx.x;
    int tx = tid & 15, ty = tid >> 4;
    int m0 = blockIdx.y * 64, n0 = blockIdx.x * 64;
    int ar = tid >> 2, ak = (tid & 3) << 2;   // A tile: row 0..63, k 0..12
    int bk = tid >> 4, bc = (tid & 15) << 2;  // B tile: k 0..15, col 0..60

    float acc[16];
    #pragma unroll
    for (int i = 0; i < 16; i++) acc[i] = 0.f;

    for (int k0 = 0; k0 < D_DIM; k0 += 16) {
        float4 av = *(const float4*)&g_xn[(size_t)(m0 + ar) * D_DIM + k0 + ak];
        As[(ak + 0) * 64 + ar] = av.x;
        As[(ak + 1) * 64 + ar] = av.y;
        As[(ak + 2) * 64 + ar] = av.z;
        As[(ak + 3) * 64 + ar] = av.w;
        float4 bv = *(const float4*)&W[(size_t)(k0 + bk) * HID + n0 + bc];
        *(float4*)&Bs[bk * 64 + bc] = bv;
        __syncthreads();
        #pragma unroll
        for (int kk = 0; kk < 16; ++kk) {
            float4 a = *(const float4*)&As[kk * 64 + (ty << 2)];
            float4 b = *(const float4*)&Bs[kk * 64 + (tx << 2)];
            FMA16(acc, a, b)
        }
        __syncthreads();
    }
    #pragma unroll
    for (int r = 0; r < 4; ++r) {
        #pragma unroll
        for (int c = 0; c < 4; ++c) {
            float s = acc[r * 4 + c];
            float sig = __fdividef(1.0f, 1.0f + __expf(-s));
            g_h[(size_t)(m0 + (ty << 2) + r) * HID + n0 + (tx << 2) + c] = s * sig;
        }
    }
}

// ---------------------------------------------------------------------------
// Kernel 3: jagged causal attention per (tile, head)
// P = silu(q k^T + bias(dt)) / 2048 (causal),  O = P @ v
// bucket(log1p) replaced by 14 exact integer thresholds.
// ---------------------------------------------------------------------------
#define PADW 68
#define SMEM_ATTN ((3 * 64 * PADW + 130 + 16) * 4 + 128 * 4 + 64)

__global__ void attn_kernel(const int* __restrict__ ts,
                            const float* __restrict__ tsw) {
    extern __shared__ float sm[];
    float* QsT = sm;                    // [d][i]  64*PADW
    float* KsT = QsT + 64 * PADW;       // [d][j], reused as PsT [j][i]
    float* Vs  = KsT + 64 * PADW;       // [j][l]
    float* tw  = Vs + 64 * PADW;        // 129 (+1 pad)
    float* thf = tw + 130;              // 16 thresholds
    int*   tqs = (int*)(thf + 16);      // 64
    int*   tks = tqs + 64;              // 64

    int tile = blockIdx.x;
    int head = blockIdx.y;
    int b, qt;
    if      (tile < 32) { b = 0; qt = tile; }
    else if (tile < 56) { b = 1; qt = tile - 32; }
    else if (tile < 72) { b = 2; qt = tile - 56; }
    else                { b = 3; qt = tile - 72; }
    int tok0 = c_off[b] + qt * 64;

    int tid = threadIdx.x;
    int tx = tid & 15, ty = tid >> 4;
    int i0 = ty << 2, j0 = tx << 2;

    // ---- load Q tile transposed: QsT[d][i]
    {
        const float* qb = g_h + 512 + head * 64;
        for (int i = tid; i < 1024; i += 256) {
            int r = i >> 4, c = (i & 15) << 2;
            float4 v = *(const float4*)&qb[(size_t)(tok0 + r) * HID + c];
            QsT[(c + 0) * PADW + r] = v.x;
            QsT[(c + 1) * PADW + r] = v.y;
            QsT[(c + 2) * PADW + r] = v.z;
            QsT[(c + 3) * PADW + r] = v.w;
        }
    }
    for (int i = tid; i < 129; i += 256) tw[i] = tsw[i];
    if (tid < 64) tqs[tid] = ts[b * N_SEQ + qt * 64 + tid];
    if (tid < 15) {
        if (tid == 0) thf[0] = 0.f;
        else {
            int k = tid;
            int t = (int)(expf((float)k)) - 9;
            if (t < 1) t = 1;
            while (t > 1 && log1pf((float)(t - 1)) >= (float)k) --t;
            while (log1pf((float)t) < (float)k) ++t;
            thf[k] = (float)t;   // min integer d with floor(log1p(d)) >= k
        }
    }

    float O[16];
    #pragma unroll
    for (int i = 0; i < 16; i++) O[i] = 0.f;

    const float* kb = g_h + 768 + head * 64;
    const float* vb = g_h + 256 + head * 64;

    for (int jt = 0; jt <= qt; ++jt) {
        __syncthreads();
        int ktok0 = c_off[b] + jt * 64;
        for (int i = tid; i < 1024; i += 256) {
            int r = i >> 4, c = (i & 15) << 2;
            float4 kv = *(const float4*)&kb[(size_t)(ktok0 + r) * HID + c];
            KsT[(c + 0) * PADW + r] = kv.x;
            KsT[(c + 1) * PADW + r] = kv.y;
            KsT[(c + 2) * PADW + r] = kv.z;
            KsT[(c + 3) * PADW + r] = kv.w;
            float4 vv = *(const float4*)&vb[(size_t)(ktok0 + r) * HID + c];
            *(float4*)&Vs[r * PADW + c] = vv;
        }
        if (tid < 64) tks[tid] = ts[b * N_SEQ + jt * 64 + tid];
        __syncthreads();

        // S = Q K^T
        float S[16];
        #pragma unroll
        for (int i = 0; i < 16; i++) S[i] = 0.f;
        #pragma unroll 8
        for (int d = 0; d < 64; ++d) {
            float4 a  = *(const float4*)&QsT[d * PADW + i0];
            float4 bb = *(const float4*)&KsT[d * PADW + j0];
            FMA16(S, a, bb)
        }
        __syncthreads();   // everyone done reading KsT

        // P = silu(S + bias)/N * causal  -> store transposed PsT[j][i] in KsT
        bool full = (jt < qt);
        #pragma unroll
        for (int r = 0; r < 4; ++r) {
            int tq = tqs[i0 + r];
            #pragma unroll
            for (int c = 0; c < 4; ++c) {
                float p = 0.f;
                if (full || (j0 + c) <= (i0 + r)) {
                    float fd = fabsf((float)(tq - tks[j0 + c]));
                    int bkt = 0;
                    #pragma unroll
                    for (int k = 1; k <= 14; ++k) bkt += (fd >= thf[k]) ? 1 : 0;
                    float s = S[r * 4 + c] + tw[bkt];
                    p = s * __fdividef(1.0f, 1.0f + __expf(-s)) * INV_N;
                }
                KsT[(j0 + c) * PADW + (i0 + r)] = p;
            }
        }
        __syncthreads();

        // O += P @ V
        #pragma unroll 8
        for (int j = 0; j < 64; ++j) {
            float4 a = *(const float4*)&KsT[j * PADW + i0];  // PsT[j][i0..]
            float4 v = *(const float4*)&Vs[j * PADW + j0];
            FMA16(O, a, v)
        }
    }

    #pragma unroll
    for (int r = 0; r < 4; ++r) {
        #pragma unroll
        for (int c = 0; c < 4; ++c) {
            g_attn[(size_t)(tok0 + i0 + r) * 256 + head * 64 + j0 + c] = O[r * 4 + c];
        }
    }
}

// ---------------------------------------------------------------------------
// Kernel 4: oin = u * LN(attn)  (LN over 256 dims)
// ---------------------------------------------------------------------------
__global__ void oin_kernel() {
    int t = blockIdx.x;
    int tid = threadIdx.x;
    float a = g_attn[(size_t)t * 256 + tid];
    float s = a, q = a * a;
    __shared__ float sbuf[18];
    #pragma unroll
    for (int o = 16; o > 0; o >>= 1) {
        s += __shfl_down_sync(0xffffffffu, s, o);
        q += __shfl_down_sync(0xffffffffu, q, o);
    }
    int w = tid >> 5;
    if ((tid & 31) == 0) { sbuf[w] = s; sbuf[w + 8] = q; }
    __syncthreads();
    if (tid == 0) {
        float S = 0.f, Q = 0.f;
        #pragma unroll
        for (int i = 0; i < 8; i++) { S += sbuf[i]; Q += sbuf[i + 8]; }
        float m = S * (1.0f / 256.0f);
        float var = Q * (1.0f / 256.0f) - m * m;
        sbuf[16] = m;
        sbuf[17] = rsqrtf(var + EPS);
    }
    __syncthreads();
    float m = sbuf[16], r = sbuf[17];
    float u = g_h[(size_t)t * HID + tid];   // u slice = h[:, 0:256]
    g_oin[(size_t)t * 256 + tid] = u * (a - m) * r;
}

// ---------------------------------------------------------------------------
// Kernel 5: out = oin @ o_w^T + o_b + x   [6400,256]@[256,512]
// ---------------------------------------------------------------------------
__global__ void gemm_out_kernel(const float* __restrict__ W,     // [512,256]
                                const float* __restrict__ bias,  // [512]
                                const float* __restrict__ x,
                                float* __restrict__ out) {
    __shared__ float As[16 * 64];
    __shared__ float Bs[16 * 64];
    int tid = threadIdx.x;
    int tx = tid & 15, ty = tid >> 4;
    int m0 = blockIdx.y * 64, n0 = blockIdx.x * 64;
    int ar = tid >> 2, ak = (tid & 3) << 2;

    float acc[16];
    #pragma unroll
    for (int i = 0; i < 16; i++) acc[i] = 0.f;

    for (int k0 = 0; k0 < 256; k0 += 16) {
        float4 av = *(const float4*)&g_oin[(size_t)(m0 + ar) * 256 + k0 + ak];
        As[(ak + 0) * 64 + ar] = av.x;
        As[(ak + 1) * 64 + ar] = av.y;
        As[(ak + 2) * 64 + ar] = av.z;
        As[(ak + 3) * 64 + ar] = av.w;
        float4 wv = *(const float4*)&W[(size_t)(n0 + ar) * 256 + k0 + ak];
        Bs[(ak + 0) * 64 + ar] = wv.x;   // Bs[k][n]
        Bs[(ak + 1) * 64 + ar] = wv.y;
        Bs[(ak + 2) * 64 + ar] = wv.z;
        Bs[(ak + 3) * 64 + ar] = wv.w;
        __syncthreads();
        #pragma unroll
        for (int kk = 0; kk < 16; ++kk) {
            float4 a = *(const float4*)&As[kk * 64 + (ty << 2)];
            float4 b = *(const float4*)&Bs[kk * 64 + (tx << 2)];
            FMA16(acc, a, b)
        }
        __syncthreads();
    }
    #pragma unroll
    for (int r = 0; r < 4; ++r) {
        int row = m0 + (ty << 2) + r;
        #pragma unroll
        for (int c = 0; c < 4; ++c) {
            int col = n0 + (tx << 2) + c;
            out[(size_t)row * D_DIM + col] =
                acc[r * 4 + c] + bias[col] + x[(size_t)row * D_DIM + col];
        }
    }
}

// ---------------------------------------------------------------------------
// Launcher
// ---------------------------------------------------------------------------
extern "C" void kernel_launch(void* const* d_in, const int* in_sizes, int n_in,
                              void* d_out, int out_size) {
    const float* x    = (const float*)d_in[0];
    const float* uvqk = (const float*)d_in[1];
    const float* o_w  = (const float*)d_in[2];
    const float* o_b  = (const float*)d_in[3];
    const float* ts_w = (const float*)d_in[4];
    const int*   ts   = (const int*)d_in[5];
    float* out = (float*)d_out;

    ln_x_kernel<<<T_TOK, 256>>>(x);
    gemm_uvqk_kernel<<<dim3(HID / 64, T_TOK / 64), 256>>>(uvqk);

    cudaFuncSetAttribute(attn_kernel,
                         cudaFuncAttributeMaxDynamicSharedMemorySize, SMEM_ATTN);
    attn_kernel<<<dim3(100, H_HEADS), 256, SMEM_ATTN>>>(ts, ts_w);

    oin_kernel<<<T_TOK, 256>>>();
    gemm_out_kernel<<<dim3(D_DIM / 64, T_TOK / 64), 256>>>(o_w, o_b, x, out);
}

// round 3
// speedup vs baseline: 3.4053x; 3.4053x over previous
#include <cuda_runtime.h>
#include <cuda_bf16.h>
#include <math.h>

// ---------------------------------------------------------------------------
// Problem constants
// ---------------------------------------------------------------------------
#define T_TOK   6400
#define D_DIM   512
#define HID     1024
#define N_SEQ   2048
#define EPS     1e-6f
#define INV_N   (1.0f/2048.0f)

__device__ __constant__ int c_off[5] = {0, 2048, 3584, 4608, 6400};

// ---------------------------------------------------------------------------
// Scratch
// ---------------------------------------------------------------------------
__device__ float g_xn  [T_TOK * D_DIM];
__device__ float g_h   [T_TOK * HID];     // u|v|q|k
__device__ float g_attn[T_TOK * 256];
__device__ float g_oin [T_TOK * 256];

// ---------------------------------------------------------------------------
// tf32 mma helpers
// ---------------------------------------------------------------------------
__device__ __forceinline__ unsigned f2tf(float x) {
    unsigned u; asm("cvt.rna.tf32.f32 %0, %1;" : "=r"(u) : "f"(x)); return u;
}
__device__ __forceinline__ void mma8(float* c, const unsigned* a, const unsigned* b) {
    asm volatile(
      "mma.sync.aligned.m16n8k8.row.col.f32.tf32.tf32.f32 "
      "{%0,%1,%2,%3}, {%4,%5,%6,%7}, {%8,%9}, {%0,%1,%2,%3};"
      : "+f"(c[0]), "+f"(c[1]), "+f"(c[2]), "+f"(c[3])
      : "r"(a[0]), "r"(a[1]), "r"(a[2]), "r"(a[3]), "r"(b[0]), "r"(b[1]));
}
__device__ __forceinline__ float silu_f(float s) {
    return s * __fdividef(1.0f, 1.0f + __expf(-s));
}

// ---------------------------------------------------------------------------
// Kernel 1: LayerNorm over D=512
// ---------------------------------------------------------------------------
__global__ void ln_x_kernel(const float* __restrict__ x) {
    int t = blockIdx.x;
    int tid = threadIdx.x;
    const float* row = x + (size_t)t * D_DIM;
    float v0 = row[tid];
    float v1 = row[tid + 256];
    float s = v0 + v1;
    float q = v0 * v0 + v1 * v1;
    __shared__ float sbuf[18];
    #pragma unroll
    for (int o = 16; o > 0; o >>= 1) {
        s += __shfl_down_sync(0xffffffffu, s, o);
        q += __shfl_down_sync(0xffffffffu, q, o);
    }
    int w = tid >> 5;
    if ((tid & 31) == 0) { sbuf[w] = s; sbuf[w + 8] = q; }
    __syncthreads();
    if (tid == 0) {
        float S = 0.f, Q = 0.f;
        #pragma unroll
        for (int i = 0; i < 8; i++) { S += sbuf[i]; Q += sbuf[i + 8]; }
        float m = S * (1.0f / D_DIM);
        float var = Q * (1.0f / D_DIM) - m * m;
        sbuf[16] = m;
        sbuf[17] = rsqrtf(var + EPS);
    }
    __syncthreads();
    float m = sbuf[16], r = sbuf[17];
    g_xn[(size_t)t * D_DIM + tid]       = (v0 - m) * r;
    g_xn[(size_t)t * D_DIM + tid + 256] = (v1 - m) * r;
}

// ---------------------------------------------------------------------------
// Kernel 2: h = silu(xn @ uvqk)  [6400,512]@[512,1024]  -- tf32 mma
// BM=128 BN=64 BK=16, 8 warps (4x2), warp tile 32x32
// ---------------------------------------------------------------------------
__global__ void gemm_uvqk_mma(const float* __restrict__ W) {
    __shared__ unsigned As[128 * 20];   // [m][k], stride 20
    __shared__ unsigned Bs[16 * 72];    // [k][n], stride 72
    int tid = threadIdx.x, lane = tid & 31, warp = tid >> 5;
    int wm = warp >> 1, wn = warp & 1;
    int m0 = blockIdx.y * 128, n0 = blockIdx.x * 64;

    float acc[2][4][4];
    #pragma unroll
    for (int a = 0; a < 2; a++)
        #pragma unroll
        for (int b = 0; b < 4; b++)
            #pragma unroll
            for (int c = 0; c < 4; c++) acc[a][b][c] = 0.f;

    int lr = tid >> 2, lk = (tid & 3) << 2;
    int bk = tid >> 4, bn = (tid & 15) << 2;
    const float* A0 = g_xn + (size_t)(m0 + lr) * D_DIM + lk;
    const float* A1 = A0 + (size_t)64 * D_DIM;

    for (int k0 = 0; k0 < D_DIM; k0 += 16) {
        float4 a0 = *(const float4*)(A0 + k0);
        float4 a1 = *(const float4*)(A1 + k0);
        float4 bv = *(const float4*)&W[(size_t)(k0 + bk) * HID + n0 + bn];
        __syncthreads();
        As[lr * 20 + lk + 0] = f2tf(a0.x);
        As[lr * 20 + lk + 1] = f2tf(a0.y);
        As[lr * 20 + lk + 2] = f2tf(a0.z);
        As[lr * 20 + lk + 3] = f2tf(a0.w);
        As[(lr + 64) * 20 + lk + 0] = f2tf(a1.x);
        As[(lr + 64) * 20 + lk + 1] = f2tf(a1.y);
        As[(lr + 64) * 20 + lk + 2] = f2tf(a1.z);
        As[(lr + 64) * 20 + lk + 3] = f2tf(a1.w);
        Bs[bk * 72 + bn + 0] = f2tf(bv.x);
        Bs[bk * 72 + bn + 1] = f2tf(bv.y);
        Bs[bk * 72 + bn + 2] = f2tf(bv.z);
        Bs[bk * 72 + bn + 3] = f2tf(bv.w);
        __syncthreads();
        #pragma unroll
        for (int ks = 0; ks < 2; ks++) {
            int kk = ks * 8 + (lane & 3);
            unsigned af[2][4];
            #pragma unroll
            for (int mm = 0; mm < 2; mm++) {
                int r = wm * 32 + mm * 16 + (lane >> 2);
                af[mm][0] = As[r * 20 + kk];
                af[mm][1] = As[(r + 8) * 20 + kk];
                af[mm][2] = As[r * 20 + kk + 4];
                af[mm][3] = As[(r + 8) * 20 + kk + 4];
            }
            #pragma unroll
            for (int nm = 0; nm < 4; nm++) {
                int cn = wn * 32 + nm * 8 + (lane >> 2);
                unsigned bf[2] = { Bs[kk * 72 + cn], Bs[(kk + 4) * 72 + cn] };
                mma8(acc[0][nm], af[0], bf);
                mma8(acc[1][nm], af[1], bf);
            }
        }
    }
    #pragma unroll
    for (int mm = 0; mm < 2; mm++) {
        #pragma unroll
        for (int nm = 0; nm < 4; nm++) {
            int r = m0 + wm * 32 + mm * 16 + (lane >> 2);
            int c = n0 + wn * 32 + nm * 8 + 2 * (lane & 3);
            *(float2*)&g_h[(size_t)r * HID + c] =
                make_float2(silu_f(acc[mm][nm][0]), silu_f(acc[mm][nm][1]));
            *(float2*)&g_h[(size_t)(r + 8) * HID + c] =
                make_float2(silu_f(acc[mm][nm][2]), silu_f(acc[mm][nm][3]));
        }
    }
}

// ---------------------------------------------------------------------------
// Kernel 3: jagged causal attention via tf32 mma
// Per block: (q-tile, head). S^T = K @ Q^T ; P^T -> SMEM ; O += P @ V
// ---------------------------------------------------------------------------
#define A_QS 0
#define A_KS (64 * 72)
#define A_VS (A_KS + 64 * 68)
#define A_PS (A_VS + 64 * 72)
#define A_AUX (A_PS + 64 * 72)
#define ATTN_WORDS (A_AUX + 132 + 16 + 64 + 64)
#define SMEM_ATTN (ATTN_WORDS * 4)

__global__ void attn_mma(const int* __restrict__ ts, const float* __restrict__ tsw) {
    extern __shared__ unsigned sm[];
    unsigned* Qs = sm + A_QS;   // [d][i] stride 72 (transposed Q)
    unsigned* Ks = sm + A_KS;   // [j][d] stride 68
    unsigned* Vs = sm + A_VS;   // [j][l] stride 72
    unsigned* Ps = sm + A_PS;   // [j][i] stride 72 (P transposed)
    float* tw  = (float*)(sm + A_AUX);  // 129 (pad 132)
    float* thf = tw + 132;              // 16
    int* tqs = (int*)(thf + 16);        // 64
    int* tks = tqs + 64;                // 64

    int tile = 99 - blockIdx.x;   // largest q-tiles first
    int head = blockIdx.y;
    int b, qt;
    if      (tile < 32) { b = 0; qt = tile; }
    else if (tile < 56) { b = 1; qt = tile - 32; }
    else if (tile < 72) { b = 2; qt = tile - 56; }
    else                { b = 3; qt = tile - 72; }
    int tok0 = c_off[b] + qt * 64;

    int tid = threadIdx.x, lane = tid & 31, warp = tid >> 5;
    int wm = warp >> 1, wn = warp & 1;

    // stage Q transposed (once per block)
    const float* qb = g_h + 512 + head * 64;
    for (int i = tid; i < 1024; i += 256) {
        int r = i >> 4, c = (i & 15) << 2;
        float4 v = *(const float4*)&qb[(size_t)(tok0 + r) * HID + c];
        Qs[(c + 0) * 72 + r] = f2tf(v.x);
        Qs[(c + 1) * 72 + r] = f2tf(v.y);
        Qs[(c + 2) * 72 + r] = f2tf(v.z);
        Qs[(c + 3) * 72 + r] = f2tf(v.w);
    }
    for (int i = tid; i < 129; i += 256) tw[i] = tsw[i];
    if (tid < 64) tqs[tid] = ts[b * N_SEQ + qt * 64 + tid];
    if (tid < 15) {
        if (tid == 0) thf[0] = 0.f;
        else {
            int k = tid;
            int t = (int)(expf((float)k)) - 9;
            if (t < 1) t = 1;
            while (t > 1 && log1pf((float)(t - 1)) >= (float)k) --t;
            while (log1pf((float)t) < (float)k) ++t;
            thf[k] = (float)t;
        }
    }
    __syncthreads();
    float th[14];
    #pragma unroll
    for (int k = 0; k < 14; k++) th[k] = thf[k + 1];

    float accO[4][4];
    #pragma unroll
    for (int a = 0; a < 4; a++)
        #pragma unroll
        for (int c = 0; c < 4; c++) accO[a][c] = 0.f;

    const float* kb = g_h + 768 + head * 64;
    const float* vb = g_h + 256 + head * 64;

    for (int jt = 0; jt <= qt; ++jt) {
        __syncthreads();
        int ktok = c_off[b] + jt * 64;
        for (int i = tid; i < 1024; i += 256) {
            int r = i >> 4, c = (i & 15) << 2;
            float4 kv = *(const float4*)&kb[(size_t)(ktok + r) * HID + c];
            float4 vv = *(const float4*)&vb[(size_t)(ktok + r) * HID + c];
            *(uint4*)&Ks[r * 68 + c] =
                make_uint4(f2tf(kv.x), f2tf(kv.y), f2tf(kv.z), f2tf(kv.w));
            *(uint4*)&Vs[r * 72 + c] =
                make_uint4(f2tf(vv.x), f2tf(vv.y), f2tf(vv.z), f2tf(vv.w));
        }
        if (tid < 64) tks[tid] = ts[b * N_SEQ + jt * 64 + tid];
        __syncthreads();

        // S^T[j][i] = sum_d K[j][d] Q[i][d]
        float accS[4][4];
        #pragma unroll
        for (int a = 0; a < 4; a++)
            #pragma unroll
            for (int c = 0; c < 4; c++) accS[a][c] = 0.f;
        #pragma unroll
        for (int ks = 0; ks < 8; ks++) {
            int kk = ks * 8 + (lane & 3);
            int jr = wm * 16 + (lane >> 2);
            unsigned af[4];
            af[0] = Ks[jr * 68 + kk];
            af[1] = Ks[(jr + 8) * 68 + kk];
            af[2] = Ks[jr * 68 + kk + 4];
            af[3] = Ks[(jr + 8) * 68 + kk + 4];
            #pragma unroll
            for (int nm = 0; nm < 4; nm++) {
                int ic = wn * 32 + nm * 8 + (lane >> 2);
                unsigned bf[2] = { Qs[kk * 72 + ic], Qs[(kk + 4) * 72 + ic] };
                mma8(accS[nm], af, bf);
            }
        }

        // bias + silu + causal -> Ps (transposed)
        bool full = (jt < qt);
        #pragma unroll
        for (int nm = 0; nm < 4; nm++) {
            #pragma unroll
            for (int e = 0; e < 4; e++) {
                int j = wm * 16 + (lane >> 2) + ((e & 2) ? 8 : 0);
                int i = wn * 32 + nm * 8 + 2 * (lane & 3) + (e & 1);
                float p = 0.f;
                if (full || j <= i) {
                    float fd = fabsf((float)(tqs[i] - tks[j]));
                    int bkt = 0;
                    #pragma unroll
                    for (int k = 0; k < 14; k++) bkt += (fd >= th[k]) ? 1 : 0;
                    float s = accS[nm][e] + tw[bkt];
                    p = silu_f(s) * INV_N;
                }
                Ps[j * 72 + i] = f2tf(p);
            }
        }
        __syncthreads();

        // O[i][l] += sum_j P[i][j] V[j][l]
        #pragma unroll
        for (int ks = 0; ks < 8; ks++) {
            int kk = ks * 8 + (lane & 3);
            int ir = wm * 16 + (lane >> 2);
            unsigned af[4];
            af[0] = Ps[kk * 72 + ir];
            af[1] = Ps[kk * 72 + ir + 8];
            af[2] = Ps[(kk + 4) * 72 + ir];
            af[3] = Ps[(kk + 4) * 72 + ir + 8];
            #pragma unroll
            for (int nm = 0; nm < 4; nm++) {
                int lc = wn * 32 + nm * 8 + (lane >> 2);
                unsigned bf[2] = { Vs[kk * 72 + lc], Vs[(kk + 4) * 72 + lc] };
                mma8(accO[nm], af, bf);
            }
        }
    }

    #pragma unroll
    for (int nm = 0; nm < 4; nm++) {
        int i = wm * 16 + (lane >> 2);
        int l = wn * 32 + nm * 8 + 2 * (lane & 3);
        *(float2*)&g_attn[(size_t)(tok0 + i) * 256 + head * 64 + l] =
            make_float2(accO[nm][0], accO[nm][1]);
        *(float2*)&g_attn[(size_t)(tok0 + i + 8) * 256 + head * 64 + l] =
            make_float2(accO[nm][2], accO[nm][3]);
    }
}

// ---------------------------------------------------------------------------
// Kernel 4: oin = u * LN(attn)
// ---------------------------------------------------------------------------
__global__ void oin_kernel() {
    int t = blockIdx.x;
    int tid = threadIdx.x;
    float a = g_attn[(size_t)t * 256 + tid];
    float s = a, q = a * a;
    __shared__ float sbuf[18];
    #pragma unroll
    for (int o = 16; o > 0; o >>= 1) {
        s += __shfl_down_sync(0xffffffffu, s, o);
        q += __shfl_down_sync(0xffffffffu, q, o);
    }
    int w = tid >> 5;
    if ((tid & 31) == 0) { sbuf[w] = s; sbuf[w + 8] = q; }
    __syncthreads();
    if (tid == 0) {
        float S = 0.f, Q = 0.f;
        #pragma unroll
        for (int i = 0; i < 8; i++) { S += sbuf[i]; Q += sbuf[i + 8]; }
        float m = S * (1.0f / 256.0f);
        float var = Q * (1.0f / 256.0f) - m * m;
        sbuf[16] = m;
        sbuf[17] = rsqrtf(var + EPS);
    }
    __syncthreads();
    float m = sbuf[16], r = sbuf[17];
    float u = g_h[(size_t)t * HID + tid];
    g_oin[(size_t)t * 256 + tid] = u * (a - m) * r;
}

// ---------------------------------------------------------------------------
// Kernel 5: out = oin @ o_w^T + o_b + x  [6400,256]@[256,512] -- tf32 mma
// ---------------------------------------------------------------------------
__global__ void gemm_out_mma(const float* __restrict__ Wo,    // [512,256]
                             const float* __restrict__ bias,  // [512]
                             const float* __restrict__ x,
                             float* __restrict__ out) {
    __shared__ unsigned As[128 * 20];
    __shared__ unsigned Bs[16 * 72];
    int tid = threadIdx.x, lane = tid & 31, warp = tid >> 5;
    int wm = warp >> 1, wn = warp & 1;
    int m0 = blockIdx.y * 128, n0 = blockIdx.x * 64;

    float acc[2][4][4];
    #pragma unroll
    for (int a = 0; a < 2; a++)
        #pragma unroll
        for (int b = 0; b < 4; b++)
            #pragma unroll
            for (int c = 0; c < 4; c++) acc[a][b][c] = 0.f;

    int lr = tid >> 2, lk = (tid & 3) << 2;
    int bn = tid & 63, bk4 = (tid >> 6) << 2;

    for (int k0 = 0; k0 < 256; k0 += 16) {
        float4 a0 = *(const float4*)&g_oin[(size_t)(m0 + lr) * 256 + k0 + lk];
        float4 a1 = *(const float4*)&g_oin[(size_t)(m0 + lr + 64) * 256 + k0 + lk];
        float4 wv = *(const float4*)&Wo[(size_t)(n0 + bn) * 256 + k0 + bk4];
        __syncthreads();
        As[lr * 20 + lk + 0] = f2tf(a0.x);
        As[lr * 20 + lk + 1] = f2tf(a0.y);
        As[lr * 20 + lk + 2] = f2tf(a0.z);
        As[lr * 20 + lk + 3] = f2tf(a0.w);
        As[(lr + 64) * 20 + lk + 0] = f2tf(a1.x);
        As[(lr + 64) * 20 + lk + 1] = f2tf(a1.y);
        As[(lr + 64) * 20 + lk + 2] = f2tf(a1.z);
        As[(lr + 64) * 20 + lk + 3] = f2tf(a1.w);
        Bs[(bk4 + 0) * 72 + bn] = f2tf(wv.x);   // transpose o_w -> [k][n]
        Bs[(bk4 + 1) * 72 + bn] = f2tf(wv.y);
        Bs[(bk4 + 2) * 72 + bn] = f2tf(wv.z);
        Bs[(bk4 + 3) * 72 + bn] = f2tf(wv.w);
        __syncthreads();
        #pragma unroll
        for (int ks = 0; ks < 2; ks++) {
            int kk = ks * 8 + (lane & 3);
            unsigned af[2][4];
            #pragma unroll
            for (int mm = 0; mm < 2; mm++) {
                int r = wm * 32 + mm * 16 + (lane >> 2);
                af[mm][0] = As[r * 20 + kk];
                af[mm][1] = As[(r + 8) * 20 + kk];
                af[mm][2] = As[r * 20 + kk + 4];
                af[mm][3] = As[(r + 8) * 20 + kk + 4];
            }
            #pragma unroll
            for (int nm = 0; nm < 4; nm++) {
                int cn = wn * 32 + nm * 8 + (lane >> 2);
                unsigned bf[2] = { Bs[kk * 72 + cn], Bs[(kk + 4) * 72 + cn] };
                mma8(acc[0][nm], af[0], bf);
                mma8(acc[1][nm], af[1], bf);
            }
        }
    }
    #pragma unroll
    for (int mm = 0; mm < 2; mm++) {
        #pragma unroll
        for (int nm = 0; nm < 4; nm++) {
            int r = m0 + wm * 32 + mm * 16 + (lane >> 2);
            int c = n0 + wn * 32 + nm * 8 + 2 * (lane & 3);
            float2 xr0 = *(const float2*)&x[(size_t)r * D_DIM + c];
            float2 xr1 = *(const float2*)&x[(size_t)(r + 8) * D_DIM + c];
            float b0 = bias[c], b1 = bias[c + 1];
            *(float2*)&out[(size_t)r * D_DIM + c] =
                make_float2(acc[mm][nm][0] + b0 + xr0.x, acc[mm][nm][1] + b1 + xr0.y);
            *(float2*)&out[(size_t)(r + 8) * D_DIM + c] =
                make_float2(acc[mm][nm][2] + b0 + xr1.x, acc[mm][nm][3] + b1 + xr1.y);
        }
    }
}

// ---------------------------------------------------------------------------
// Launcher
// ---------------------------------------------------------------------------
extern "C" void kernel_launch(void* const* d_in, const int* in_sizes, int n_in,
                              void* d_out, int out_size) {
    const float* x    = (const float*)d_in[0];
    const float* uvqk = (const float*)d_in[1];
    const float* o_w  = (const float*)d_in[2];
    const float* o_b  = (const float*)d_in[3];
    const float* ts_w = (const float*)d_in[4];
    const int*   ts   = (const int*)d_in[5];
    float* out = (float*)d_out;

    ln_x_kernel<<<T_TOK, 256>>>(x);
    gemm_uvqk_mma<<<dim3(HID / 64, T_TOK / 128), 256>>>(uvqk);

    cudaFuncSetAttribute(attn_mma,
                         cudaFuncAttributeMaxDynamicSharedMemorySize, SMEM_ATTN);
    attn_mma<<<dim3(100, 4), 256, SMEM_ATTN>>>(ts, ts_w);

    oin_kernel<<<T_TOK, 256>>>();
    gemm_out_mma<<<dim3(D_DIM / 64, T_TOK / 128), 256>>>(o_w, o_b, x, out);
}